// round 5
// baseline (speedup 1.0000x reference)
#include <cuda_runtime.h>
#include <cuda_bf16.h>
#include <math.h>

#define Bn 16
#define Nn 2048
#define Fn 64
#define Tn 32
#define CHUNKS 64              // chunks per batch
#define NC (Nn / CHUNKS)       // 32 nodes per chunk
#define SEG 16                 // nodes per barrier-free segment
#define NSEG (NC / SEG)        // 2 segments
#define NBLK (Bn * CHUNKS)     // 1024 reduce blocks

// Partial accumulators: [block][0=lhs1,1=R2][f*t]  (16 MB)
__device__ float g_partial[NBLK][2][Fn * Tn];
// Per-batch reduced sums: [b][0=lhs1,1=R2][f*t]  (512 KB)
__device__ float g_sum[Bn][2 * Fn * Tn];

// ---------------------------------------------------------------------------
// Pass 1: stream x once (256 MB). Barrier-free 16-node segments.
//   accL[f][t] += U1[n] * x[n,f,t]                      (register)
//   red[k][w][t] = sum_{f in warp} U3[f] * x[n,f,t]     (smem stage)
//   rsum[k][t]  = sum_w red[k][w][t]                    (cooperative)
//   accR[f][t] += sum_n U2[f,n] * rsum[k][t]
// Warp w owns f in [8w, 8w+8); lane = t. Coalesced 128B LDG.32 (streaming).
// Only 2 barriers per 16-node segment -> loads pipeline deeply.
// ---------------------------------------------------------------------------
__global__ __launch_bounds__(256, 5)
void reduce_kernel(const float* __restrict__ x,
                   const float* __restrict__ U1,
                   const float* __restrict__ U2,
                   const float* __restrict__ U3)
{
    const int blk  = blockIdx.x;        // 0..NBLK-1
    const int b    = blk >> 6;          // / CHUNKS
    const int c    = blk & (CHUNKS - 1);
    const int n0   = c * NC;
    const int tid  = threadIdx.x;
    const int w    = tid >> 5;          // warp 0..7
    const int lane = tid & 31;          // = t

    __shared__ float U2s[NC][Fn];       // U2s[nn][f] = U2[f*N + n0+nn]  (8 KB)
    __shared__ float U3s[Fn];
    __shared__ float U1s[NC];
    __shared__ float red[SEG][8][32];   // warp-partials of r  (16 KB, reused)
    __shared__ float rsum[SEG][32];     // reduced r           (2 KB, reused)

    if (tid < Fn) U3s[tid] = U3[tid];
    if (tid < NC) U1s[tid] = U1[n0 + tid];
    for (int i = tid; i < NC * Fn; i += 256) {
        int f  = i >> 5;                // i / NC  (NC == 32)
        int nn = i & (NC - 1);
        U2s[nn][f] = U2[f * Nn + n0 + nn];
    }
    __syncthreads();

    float accL[8], accR[8];
#pragma unroll
    for (int j = 0; j < 8; j++) { accL[j] = 0.f; accR[j] = 0.f; }

    const float* xb = x + ((size_t)b * Nn + n0) * (Fn * Tn);
    const int fbase = w * 8;
    float u3r[8];
#pragma unroll
    for (int j = 0; j < 8; j++) u3r[j] = U3s[fbase + j];

    for (int seg = 0; seg < NSEG; seg++) {
        // ---- Phase A: barrier-free streaming over 16 nodes ----
#pragma unroll 2
        for (int k = 0; k < SEG; k++) {
            const int nn = seg * SEG + k;
            const float* xn = xb + (size_t)nn * (Fn * Tn) + fbase * Tn + lane;
            float v[8];
#pragma unroll
            for (int j = 0; j < 8; j++)
                v[j] = __ldcs(xn + j * Tn);   // streaming: don't pollute L2

            const float u1n = U1s[nn];
            float r = 0.f;
#pragma unroll
            for (int j = 0; j < 8; j++) {
                accL[j] = fmaf(u1n, v[j], accL[j]);
                r = fmaf(u3r[j], v[j], r);
            }
            red[k][w][lane] = r;
        }
        __syncthreads();

        // ---- Phase B1: reduce r across warps (512 vals, 2 per thread) ----
#pragma unroll
        for (int h = 0; h < 2; h++) {
            int i = tid + h * 256;
            int k = i >> 5;
            int t = i & 31;
            float s = 0.f;
#pragma unroll
            for (int w2 = 0; w2 < 8; w2++) s += red[k][w2][t];
            rsum[k][t] = s;
        }
        __syncthreads();

        // ---- Phase B2: accR accumulation (reads rsum; next seg's writes to
        //      red are benign, rsum rewrite is fenced by the next barrier) ----
#pragma unroll
        for (int k = 0; k < SEG; k++) {
            const int nn = seg * SEG + k;
            const float rt = rsum[k][lane];
#pragma unroll
            for (int j = 0; j < 8; j++)
                accR[j] = fmaf(U2s[nn][fbase + j], rt, accR[j]);
        }
    }

    float* pl = &g_partial[blk][0][0];
    float* pr = &g_partial[blk][1][0];
#pragma unroll
    for (int j = 0; j < 8; j++) {
        pl[(fbase + j) * Tn + lane] = accL[j];
        pr[(fbase + j) * Tn + lane] = accR[j];
    }
}

// ---------------------------------------------------------------------------
// Pass 1.5: sum the CHUNKS chunk-partials per batch, full-grid parallelism.
// 65536 outputs, one thread each; reads 16 MB (largely L2-resident since x
// was loaded with .cs and didn't evict it).
// ---------------------------------------------------------------------------
__global__ __launch_bounds__(256)
void sum_partials()
{
    const int idx = blockIdx.x * 256 + threadIdx.x;  // 0..65535
    const int b = idx >> 12;                          // / 4096
    const int i = idx & 4095;
    const float* p = &g_partial[b * CHUNKS][0][0] + i;
    float s = 0.f;
#pragma unroll 8
    for (int c = 0; c < CHUNKS; c++)
        s += p[(size_t)c * (2 * Fn * Tn)];
    g_sum[b][i] = s;
}

// ---------------------------------------------------------------------------
// Pass 2: per-batch epilogue (grid = B, 1024 threads). Tiny.
// ---------------------------------------------------------------------------
__global__ __launch_bounds__(1024, 1)
void epilogue_kernel(const float* __restrict__ b_e,
                     const float* __restrict__ V_e,
                     float* __restrict__ out)
{
    const int b   = blockIdx.x;
    const int tid = threadIdx.x;

    __shared__ float Ls[Fn * Tn];      // lhs1[f][t]
    __shared__ float Rs[Fn * Tn];      // R2[f][s]
    __shared__ float sig_sh[Tn * Tn];  // sig[s][t]
    __shared__ float VeT[Tn * Tn];     // V_e transposed: VeT[t][u]

    for (int i = tid; i < Fn * Tn; i += 1024) {
        Ls[i] = g_sum[b][i];
        Rs[i] = g_sum[b][Fn * Tn + i];
    }
    {
        int u = tid >> 5, t = tid & 31;
        VeT[t * Tn + u] = V_e[u * Tn + t];
    }
    __syncthreads();

    // product + sigmoid: thread = (t = lane, s = warp)
    {
        const int t = tid & 31;
        const int s = tid >> 5;
        float p = 0.f;
#pragma unroll
        for (int f = 0; f < Fn; f++)
            p = fmaf(Ls[f * Tn + t], Rs[f * Tn + s], p);
        p += b_e[t * Tn + s];
        sig_sh[s * Tn + t] = 1.f / (1.f + expf(-p));
    }
    __syncthreads();

    // E + column softmax over u: thread = (u = lane, s = warp)
    {
        const int u = tid & 31;
        const int s = tid >> 5;
        float e = 0.f;
#pragma unroll
        for (int t = 0; t < Tn; t++)
            e = fmaf(VeT[t * Tn + u], sig_sh[s * Tn + t], e);

        float m = e;
#pragma unroll
        for (int o = 16; o; o >>= 1)
            m = fmaxf(m, __shfl_xor_sync(0xffffffffu, m, o));
        float ex = expf(e - m);
        float ssum = ex;
#pragma unroll
        for (int o = 16; o; o >>= 1)
            ssum += __shfl_xor_sync(0xffffffffu, ssum, o);

        out[b * Tn * Tn + u * Tn + s] = ex / ssum;
    }
}

extern "C" void kernel_launch(void* const* d_in, const int* in_sizes, int n_in,
                              void* d_out, int out_size)
{
    const float* x   = (const float*)d_in[0];
    const float* U1  = (const float*)d_in[1];
    const float* U2  = (const float*)d_in[2];
    const float* U3  = (const float*)d_in[3];
    const float* b_e = (const float*)d_in[4];
    const float* V_e = (const float*)d_in[5];
    float* out = (float*)d_out;

    reduce_kernel<<<NBLK, 256>>>(x, U1, U2, U3);
    sum_partials<<<(Bn * 2 * Fn * Tn) / 256, 256>>>();
    epilogue_kernel<<<Bn, 1024>>>(b_e, V_e, out);
}

// round 6
// speedup vs baseline: 1.3202x; 1.3202x over previous
#include <cuda_runtime.h>
#include <cuda_bf16.h>
#include <math.h>

#define Bn 16
#define Nn 2048
#define Fn 64
#define Tn 32
#define CHUNKS 128             // chunks per batch
#define NC (Nn / CHUNKS)       // 16 nodes per chunk
#define NBLK (Bn * CHUNKS)     // 2048 reduce blocks
#define GROUPS 4               // chunk-groups for two-stage partial sum
#define CPG (CHUNKS / GROUPS)  // 32 chunks per group

// Partial accumulators: [block][0=lhs1,1=R2][f*t]  (32 MB)
__device__ float g_partial[NBLK][2][Fn * Tn];
// Group-level mids: [group][b][i]  (1 MB)
__device__ float g_mid[GROUPS][Bn][2 * Fn * Tn];

// ---------------------------------------------------------------------------
// Pass 1 (identical to the measured-fast R4 version): stream x once (256 MB).
// Barrier-free mainloop: all 16 nodes' loads pipeline, then ONE barrier,
// then the cross-warp r-reduction and R2 accumulation.
// Warp w owns f in [8w, 8w+8); lane = t. Coalesced 128B LDG.32.
// ---------------------------------------------------------------------------
__global__ __launch_bounds__(256, 5)
void reduce_kernel(const float* __restrict__ x,
                   const float* __restrict__ U1,
                   const float* __restrict__ U2,
                   const float* __restrict__ U3)
{
    const int blk  = blockIdx.x;        // 0..NBLK-1
    const int b    = blk >> 7;          // / CHUNKS
    const int c    = blk & (CHUNKS - 1);
    const int n0   = c * NC;
    const int tid  = threadIdx.x;
    const int w    = tid >> 5;          // warp 0..7
    const int lane = tid & 31;          // = t

    __shared__ float U2s[NC][Fn];       // U2s[nn][f] = U2[f*N + n0+nn]
    __shared__ float U3s[Fn];
    __shared__ float U1s[NC];
    __shared__ float red[NC][8][32];    // warp-partials of r  (16 KB)
    __shared__ float rsum[NC][32];      // reduced r           (2 KB)

    if (tid < Fn) U3s[tid] = U3[tid];
    if (tid < NC) U1s[tid] = U1[n0 + tid];
    for (int i = tid; i < NC * Fn; i += 256) {
        int f  = i >> 4;                // i / NC  (NC == 16)
        int nn = i & (NC - 1);
        U2s[nn][f] = U2[f * Nn + n0 + nn];
    }
    __syncthreads();

    float accL[8];
#pragma unroll
    for (int j = 0; j < 8; j++) accL[j] = 0.f;

    const float* xb = x + ((size_t)b * Nn + n0) * (Fn * Tn);
    const int fbase = w * 8;
    float u3r[8];
#pragma unroll
    for (int j = 0; j < 8; j++) u3r[j] = U3s[fbase + j];

    // ---- Phase A: barrier-free streaming ----
#pragma unroll 2
    for (int nn = 0; nn < NC; nn++) {
        const float* xn = xb + (size_t)nn * (Fn * Tn) + fbase * Tn + lane;
        float v[8];
#pragma unroll
        for (int j = 0; j < 8; j++)
            v[j] = xn[j * Tn];

        const float u1n = U1s[nn];
        float r = 0.f;
#pragma unroll
        for (int j = 0; j < 8; j++) {
            accL[j] = fmaf(u1n, v[j], accL[j]);
            r = fmaf(u3r[j], v[j], r);
        }
        red[nn][w][lane] = r;
    }
    __syncthreads();

    // ---- Phase B: reduce r across warps, then R2 accumulation ----
#pragma unroll
    for (int h = 0; h < 2; h++) {
        int i  = tid + h * 256;
        int nn = i >> 5;
        int t  = i & 31;
        float s = 0.f;
#pragma unroll
        for (int w2 = 0; w2 < 8; w2++) s += red[nn][w2][t];
        rsum[nn][t] = s;
    }
    __syncthreads();

    float accR[8];
#pragma unroll
    for (int j = 0; j < 8; j++) accR[j] = 0.f;
#pragma unroll
    for (int nn = 0; nn < NC; nn++) {
        const float rt = rsum[nn][lane];
#pragma unroll
        for (int j = 0; j < 8; j++)
            accR[j] = fmaf(U2s[nn][fbase + j], rt, accR[j]);
    }

    float* pl = &g_partial[blk][0][0];
    float* pr = &g_partial[blk][1][0];
#pragma unroll
    for (int j = 0; j < 8; j++) {
        pl[(fbase + j) * Tn + lane] = accL[j];
        pr[(fbase + j) * Tn + lane] = accR[j];
    }
}

// ---------------------------------------------------------------------------
// Pass 1.5: stage-1 partial sum. 65536 threads; thread (g,b,i4) sums 32
// chunks of one float4 (LDG.128, MLP-unrolled). 4x parallelism + 4x fewer
// load instructions vs the single-stage version.
// ---------------------------------------------------------------------------
__global__ __launch_bounds__(256)
void sum_partials()
{
    const int idx = blockIdx.x * 256 + threadIdx.x;  // 0..65535
    const int g  = idx >> 14;          // group 0..3
    const int b  = (idx >> 10) & 15;   // batch
    const int i4 = idx & 1023;         // float4 index within 4096 floats

    const float4* p = (const float4*)(&g_partial[b * CHUNKS + g * CPG][0][0]) + i4;
    float4 s = make_float4(0.f, 0.f, 0.f, 0.f);
#pragma unroll 8
    for (int c = 0; c < CPG; c++) {
        float4 v = p[(size_t)c * (2 * Fn * Tn / 4)];
        s.x += v.x; s.y += v.y; s.z += v.z; s.w += v.w;
    }
    ((float4*)&g_mid[g][b][0])[i4] = s;
}

// ---------------------------------------------------------------------------
// Pass 2: per-batch epilogue (grid = B, 1024 threads). Sums the 4 group
// mids inline, then product->sigmoid->V_e->column softmax. Tiny.
// ---------------------------------------------------------------------------
__global__ __launch_bounds__(1024, 1)
void epilogue_kernel(const float* __restrict__ b_e,
                     const float* __restrict__ V_e,
                     float* __restrict__ out)
{
    const int b   = blockIdx.x;
    const int tid = threadIdx.x;

    __shared__ float Ls[Fn * Tn];      // lhs1[f][t]
    __shared__ float Rs[Fn * Tn];      // R2[f][s]
    __shared__ float sig_sh[Tn * Tn];  // sig[s][t]
    __shared__ float VeT[Tn * Tn];     // V_e transposed: VeT[t][u]

    for (int i = tid; i < Fn * Tn; i += 1024) {
        float sL = 0.f, sR = 0.f;
#pragma unroll
        for (int g = 0; g < GROUPS; g++) {
            sL += g_mid[g][b][i];
            sR += g_mid[g][b][Fn * Tn + i];
        }
        Ls[i] = sL;
        Rs[i] = sR;
    }
    {
        int u = tid >> 5, t = tid & 31;
        VeT[t * Tn + u] = V_e[u * Tn + t];
    }
    __syncthreads();

    // product + sigmoid: thread = (t = lane, s = warp)
    {
        const int t = tid & 31;
        const int s = tid >> 5;
        float p = 0.f;
#pragma unroll
        for (int f = 0; f < Fn; f++)
            p = fmaf(Ls[f * Tn + t], Rs[f * Tn + s], p);
        p += b_e[t * Tn + s];
        sig_sh[s * Tn + t] = 1.f / (1.f + expf(-p));
    }
    __syncthreads();

    // E + column softmax over u: thread = (u = lane, s = warp)
    {
        const int u = tid & 31;
        const int s = tid >> 5;
        float e = 0.f;
#pragma unroll
        for (int t = 0; t < Tn; t++)
            e = fmaf(VeT[t * Tn + u], sig_sh[s * Tn + t], e);

        float m = e;
#pragma unroll
        for (int o = 16; o; o >>= 1)
            m = fmaxf(m, __shfl_xor_sync(0xffffffffu, m, o));
        float ex = expf(e - m);
        float ssum = ex;
#pragma unroll
        for (int o = 16; o; o >>= 1)
            ssum += __shfl_xor_sync(0xffffffffu, ssum, o);

        out[b * Tn * Tn + u * Tn + s] = ex / ssum;
    }
}

extern "C" void kernel_launch(void* const* d_in, const int* in_sizes, int n_in,
                              void* d_out, int out_size)
{
    const float* x   = (const float*)d_in[0];
    const float* U1  = (const float*)d_in[1];
    const float* U2  = (const float*)d_in[2];
    const float* U3  = (const float*)d_in[3];
    const float* b_e = (const float*)d_in[4];
    const float* V_e = (const float*)d_in[5];
    float* out = (float*)d_out;

    reduce_kernel<<<NBLK, 256>>>(x, U1, U2, U3);
    sum_partials<<<(GROUPS * Bn * 2 * Fn * Tn / 4) / 256, 256>>>();
    epilogue_kernel<<<Bn, 1024>>>(b_e, V_e, out);
}